// round 6
// baseline (speedup 1.0000x reference)
#include <cuda_runtime.h>
#include <cuda_bf16.h>
#include <cstdint>

#define N_LEVELS 14
#define LOG2_T   19
#define T_MASK   ((1u << LOG2_T) - 1u)
#define P1       2654435761u
#define P2       805459861u
#define NTHREADS 128
#define WIDTH    64
#define W1_STRIDE 40   // 36 inputs padded to 40 bf16 = 5 uint4 per output row

typedef unsigned long long ull;

// ---- constant-memory weights (filled per launch via prep kernel + memcpy) ----
__constant__ uint4 cW1q[WIDTH * 5];    // [j][q]: 8 bf16 per uint4, inputs transposed
__constant__ uint4 cW2q[WIDTH * 8];    // [j][q]
__constant__ float cMISC[332];         // [0:192) W3t (j*64+i), [192:256) b1, [256:320) b2, [320:323) b3, [323:329) bbox

// ---- device scratch (same layouts, written by prep kernel) ----
__device__ uint4 gW1s[WIDTH * 5];
__device__ uint4 gW2s[WIDTH * 8];
__device__ float gMISC[332];

union U4B { uint4 u; __nv_bfloat162 b[4]; };
union B2U { __nv_bfloat162 b; uint32_t u; };

__device__ __forceinline__ float tanh_fast(float x) {
    float y; asm("tanh.approx.f32 %0, %1;" : "=f"(y) : "f"(x)); return y;
}

__global__ void __launch_bounds__(256)
prep_kernel(const float* __restrict__ W1, const float* __restrict__ W2,
            const float* __restrict__ W3, const float* __restrict__ b1,
            const float* __restrict__ b2, const float* __restrict__ b3,
            const float* __restrict__ bbox)
{
    int t = threadIdx.x;
    __nv_bfloat16* w1h = (__nv_bfloat16*)gW1s;
    for (int i = t; i < WIDTH * W1_STRIDE; i += 256) {
        int j = i / W1_STRIDE, k = i % W1_STRIDE;
        w1h[i] = __float2bfloat16(k < 36 ? W1[k * WIDTH + j] : 0.f);
    }
    __nv_bfloat16* w2h = (__nv_bfloat16*)gW2s;
    for (int i = t; i < WIDTH * WIDTH; i += 256) {
        int j = i >> 6, k = i & 63;
        w2h[i] = __float2bfloat16(W2[k * WIDTH + j]);
    }
    for (int i = t; i < WIDTH * 3; i += 256) {
        int col = i / 3, r = i % 3;
        gMISC[r * WIDTH + col] = W3[i];
    }
    if (t < WIDTH) { gMISC[192 + t] = b1[t]; gMISC[256 + t] = b2[t]; }
    if (t < 3) gMISC[320 + t] = b3[t];
    if (t < 6) gMISC[323 + t] = bbox[t];
}

__global__ void __launch_bounds__(NTHREADS, 4)
deformnet_kernel(const float* __restrict__ x,
                 const float* __restrict__ e,
                 const float* __restrict__ tables,
                 float* __restrict__ out, int n)
{
    int idx = blockIdx.x * NTHREADS + threadIdx.x;
    if (idx >= n) return;

    const float lo0 = cMISC[323], lo1 = cMISC[324], lo2 = cMISC[325];
    const float hi0 = cMISC[326], hi1 = cMISC[327], hi2 = cMISC[328];

    // per-point global loads up front
    const float4* e4p = (const float4*)(e + (size_t)idx * 8);
    float4 ea = __ldg(&e4p[0]);
    float4 eb = __ldg(&e4p[1]);

    float xn0 = (x[idx * 3 + 0] - lo0) / (hi0 - lo0);
    float xn1 = (x[idx * 3 + 1] - lo1) / (hi1 - lo1);
    float xn2 = (x[idx * 3 + 2] - lo2) / (hi2 - lo2);

    // resolutions = floor(16 * 1.32^l)
    const float res_tab[N_LEVELS] = {16.f, 21.f, 27.f, 36.f, 48.f, 64.f, 84.f,
                                     111.f, 147.f, 194.f, 256.f, 339.f, 447.f, 590.f};

    __nv_bfloat162 inp2[20];
    const ull* __restrict__ tabs = (const ull*)tables;

    // ---- encode: 2 levels per batch (16 gathers in flight) ----
    #pragma unroll
    for (int lp = 0; lp < 7; lp++) {
        float wxs[2], wys[2], wzs[2];
        unsigned hidx[16];
        #pragma unroll
        for (int s = 0; s < 2; s++) {
            const int l = lp * 2 + s;
            const float r = res_tab[l];
            float px = xn0 * r, py = xn1 * r, pz = xn2 * r;
            float bx = floorf(px), by = floorf(py), bz = floorf(pz);
            float fx = px - bx, fy = py - by, fz = pz - bz;
            wxs[s] = fx * fx * (3.f - 2.f * fx);
            wys[s] = fy * fy * (3.f - 2.f * fy);
            wzs[s] = fz * fz * (3.f - 2.f * fz);
            unsigned ix = (unsigned)bx, iy = (unsigned)by, iz = (unsigned)bz;
            unsigned hx0 = ix,      hx1 = ix + 1u;
            unsigned hy0 = iy * P1, hy1 = (iy + 1u) * P1;
            unsigned hz0 = iz * P2, hz1 = (iz + 1u) * P2;
            const unsigned base = (unsigned)l << LOG2_T;
            hidx[s * 8 + 0] = base + ((hx0 ^ hy0 ^ hz0) & T_MASK);
            hidx[s * 8 + 1] = base + ((hx0 ^ hy0 ^ hz1) & T_MASK);
            hidx[s * 8 + 2] = base + ((hx0 ^ hy1 ^ hz0) & T_MASK);
            hidx[s * 8 + 3] = base + ((hx0 ^ hy1 ^ hz1) & T_MASK);
            hidx[s * 8 + 4] = base + ((hx1 ^ hy0 ^ hz0) & T_MASK);
            hidx[s * 8 + 5] = base + ((hx1 ^ hy0 ^ hz1) & T_MASK);
            hidx[s * 8 + 6] = base + ((hx1 ^ hy1 ^ hz0) & T_MASK);
            hidx[s * 8 + 7] = base + ((hx1 ^ hy1 ^ hz1) & T_MASK);
        }
        ull cc[16];
        #pragma unroll
        for (int q = 0; q < 16; q++) cc[q] = __ldg(&tabs[hidx[q]]);

        #pragma unroll
        for (int s = 0; s < 2; s++) {
            float wx = wxs[s], wy = wys[s], wz = wzs[s];
            float ux = 1.f - wx, uy = 1.f - wy, uz = 1.f - wz;
            float w00 = ux * uy, w01 = ux * wy, w10 = wx * uy, w11 = wx * wy;
            float cw[8] = { w00 * uz, w00 * wz, w01 * uz, w01 * wz,
                            w10 * uz, w10 * wz, w11 * uz, w11 * wz };
            float a0 = 0.f, a1 = 0.f;
            #pragma unroll
            for (int q = 0; q < 8; q++) {
                float2 c = *(float2*)&cc[s * 8 + q];
                a0 = fmaf(cw[q], c.x, a0);
                a1 = fmaf(cw[q], c.y, a1);
            }
            inp2[lp * 2 + s] = __floats2bfloat162_rn(a0, a1);
        }
    }

    inp2[14] = __floats2bfloat162_rn(ea.x, ea.y);
    inp2[15] = __floats2bfloat162_rn(ea.z, ea.w);
    inp2[16] = __floats2bfloat162_rn(eb.x, eb.y);
    inp2[17] = __floats2bfloat162_rn(eb.z, eb.w);
    inp2[18] = __floats2bfloat162_rn(0.f, 0.f);
    inp2[19] = inp2[18];

    const __nv_bfloat162 zero2 = __floats2bfloat162_rn(0.f, 0.f);

    // ---- layer 1: [36] -> [64], tanh (weights via constant port) ----
    __nv_bfloat162 h1p[32];
    float h_prev = 0.f;
    #pragma unroll
    for (int j = 0; j < WIDTH; j++) {
        __nv_bfloat162 acc0 = zero2, acc1 = zero2;
        #pragma unroll
        for (int q = 0; q < 5; q++) {
            U4B u; u.u = cW1q[j * 5 + q];
            acc0 = __hfma2(inp2[4 * q + 0], u.b[0], acc0);
            acc1 = __hfma2(inp2[4 * q + 1], u.b[1], acc1);
            acc0 = __hfma2(inp2[4 * q + 2], u.b[2], acc0);
            acc1 = __hfma2(inp2[4 * q + 3], u.b[3], acc1);
        }
        float2 s0 = __bfloat1622float2(acc0);
        float2 s1 = __bfloat1622float2(acc1);
        float h = tanh_fast(s0.x + s0.y + s1.x + s1.y + cMISC[192 + j]);
        if (j & 1) h1p[j >> 1] = __floats2bfloat162_rn(h_prev, h); else h_prev = h;
    }

    // ---- layer 2: [64] -> [64], tanh ----
    __nv_bfloat162 h2p[32];
    #pragma unroll
    for (int j = 0; j < WIDTH; j++) {
        __nv_bfloat162 acc0 = zero2, acc1 = zero2;
        #pragma unroll
        for (int q = 0; q < 8; q++) {
            U4B u; u.u = cW2q[j * 8 + q];
            acc0 = __hfma2(h1p[4 * q + 0], u.b[0], acc0);
            acc1 = __hfma2(h1p[4 * q + 1], u.b[1], acc1);
            acc0 = __hfma2(h1p[4 * q + 2], u.b[2], acc0);
            acc1 = __hfma2(h1p[4 * q + 3], u.b[3], acc1);
        }
        float2 s0 = __bfloat1622float2(acc0);
        float2 s1 = __bfloat1622float2(acc1);
        float h = tanh_fast(s0.x + s0.y + s1.x + s1.y + cMISC[256 + j]);
        if (j & 1) h2p[j >> 1] = __floats2bfloat162_rn(h_prev, h); else h_prev = h;
    }

    // ---- layer 3: [64] -> [3] (fp32 from constant) ----
    float o0 = cMISC[320], o1 = cMISC[321], o2 = cMISC[322];
    #pragma unroll
    for (int i = 0; i < 32; i++) {
        float2 hv = __bfloat1622float2(h2p[i]);
        o0 = fmaf(hv.x, cMISC[0 * WIDTH + 2 * i],     o0);
        o0 = fmaf(hv.y, cMISC[0 * WIDTH + 2 * i + 1], o0);
        o1 = fmaf(hv.x, cMISC[1 * WIDTH + 2 * i],     o1);
        o1 = fmaf(hv.y, cMISC[1 * WIDTH + 2 * i + 1], o1);
        o2 = fmaf(hv.x, cMISC[2 * WIDTH + 2 * i],     o2);
        o2 = fmaf(hv.y, cMISC[2 * WIDTH + 2 * i + 1], o2);
    }

    out[idx * 3 + 0] = (o0 + xn0) * (hi0 - lo0) + lo0;
    out[idx * 3 + 1] = (o1 + xn1) * (hi1 - lo1) + lo1;
    out[idx * 3 + 2] = (o2 + xn2) * (hi2 - lo2) + lo2;
}

extern "C" void kernel_launch(void* const* d_in, const int* in_sizes, int n_in,
                              void* d_out, int out_size)
{
    const float* x      = (const float*)d_in[0];
    const float* e      = (const float*)d_in[1];
    const float* tables = (const float*)d_in[2];
    const float* W1     = (const float*)d_in[3];
    const float* b1     = (const float*)d_in[4];
    const float* W2     = (const float*)d_in[5];
    const float* b2     = (const float*)d_in[6];
    const float* W3     = (const float*)d_in[7];
    const float* b3     = (const float*)d_in[8];
    const float* bbox   = (const float*)d_in[9];
    float* out = (float*)d_out;

    prep_kernel<<<1, 256>>>(W1, W2, W3, b1, b2, b3, bbox);

    void *pW1s = nullptr, *pW2s = nullptr, *pMISC = nullptr;
    cudaGetSymbolAddress(&pW1s, gW1s);
    cudaGetSymbolAddress(&pW2s, gW2s);
    cudaGetSymbolAddress(&pMISC, gMISC);
    cudaMemcpyToSymbolAsync(cW1q, pW1s, sizeof(gW1s), 0, cudaMemcpyDeviceToDevice, 0);
    cudaMemcpyToSymbolAsync(cW2q, pW2s, sizeof(gW2s), 0, cudaMemcpyDeviceToDevice, 0);
    cudaMemcpyToSymbolAsync(cMISC, pMISC, sizeof(gMISC), 0, cudaMemcpyDeviceToDevice, 0);

    int n = in_sizes[0] / 3;
    int grid = (n + NTHREADS - 1) / NTHREADS;
    deformnet_kernel<<<grid, NTHREADS>>>(x, e, tables, out, n);
}

// round 7
// speedup vs baseline: 1.1708x; 1.1708x over previous
#include <cuda_runtime.h>
#include <cuda_bf16.h>
#include <cstdint>

#define N_LEVELS 14
#define LOG2_T   19
#define T_MASK   ((1u << LOG2_T) - 1u)
#define P1       2654435761u
#define P2       805459861u
#define NTHREADS 128
#define WIDTH    64
#define W1_STRIDE 40   // 36 padded to 40 bf16 = 5 float4 per output row

typedef unsigned long long ull;

__device__ __forceinline__ float tanh_fast(float x) {
    float y; asm("tanh.approx.f32 %0, %1;" : "=f"(y) : "f"(x)); return y;
}

union F4B2 { float4 f4; __nv_bfloat162 b2[4]; };
union U2B2 { uint2 u; __nv_bfloat162 b[2]; };

__device__ __forceinline__ uint32_t bf2u(float lo, float hi) {
    __nv_bfloat162 t = __floats2bfloat162_rn(lo, hi);
    return *(uint32_t*)&t;
}

__global__ void __launch_bounds__(NTHREADS, 5)
deformnet_kernel(const float* __restrict__ x,
                 const float* __restrict__ e,
                 const float* __restrict__ tables,
                 const float* __restrict__ W1, const float* __restrict__ b1,
                 const float* __restrict__ W2, const float* __restrict__ b2,
                 const float* __restrict__ W3, const float* __restrict__ b3,
                 const float* __restrict__ bbox,
                 float* __restrict__ out, int n)
{
    // bf16 transposed weights (row j = output, cols = inputs, paired)
    __shared__ __align__(16) __nv_bfloat16 sW1h[WIDTH * W1_STRIDE]; // 5120 B
    __shared__ __align__(16) __nv_bfloat16 sW2h[WIDTH * WIDTH];     // 8192 B
    __shared__ __align__(16) float sW3[3 * WIDTH];                  //  768 B
    __shared__ float sB1[WIDTH], sB2[WIDTH], sB3[3];
    __shared__ float sBB[6];
    // per-thread feature staging: 36 bf16 = 9 uint2 (72 B row)
    __shared__ uint2 sFeat[NTHREADS][9];                             // 9216 B

    for (int t = threadIdx.x; t < WIDTH * W1_STRIDE; t += NTHREADS) {
        int j = t / W1_STRIDE, i = t % W1_STRIDE;
        float v = (i < 36) ? W1[i * WIDTH + j] : 0.f;
        sW1h[t] = __float2bfloat16(v);
    }
    for (int t = threadIdx.x; t < WIDTH * WIDTH; t += NTHREADS) {
        int i = t / WIDTH, j = t % WIDTH;
        sW2h[j * WIDTH + i] = __float2bfloat16(W2[t]);
    }
    for (int t = threadIdx.x; t < WIDTH * 3; t += NTHREADS) {
        int i = t / 3, j = t % 3;
        sW3[j * WIDTH + i] = W3[t];
    }
    if (threadIdx.x < WIDTH) { sB1[threadIdx.x] = b1[threadIdx.x]; sB2[threadIdx.x] = b2[threadIdx.x]; }
    if (threadIdx.x < 3) sB3[threadIdx.x] = b3[threadIdx.x];
    if (threadIdx.x < 6) sBB[threadIdx.x] = bbox[threadIdx.x];
    __syncthreads();

    const int tid = threadIdx.x;
    int idx = blockIdx.x * NTHREADS + tid;
    if (idx >= n) return;

    const float lo0 = sBB[0], lo1 = sBB[1], lo2 = sBB[2];
    const float hi0 = sBB[3], hi1 = sBB[4], hi2 = sBB[5];

    float xn0 = (x[idx * 3 + 0] - lo0) / (hi0 - lo0);
    float xn1 = (x[idx * 3 + 1] - lo1) / (hi1 - lo1);
    float xn2 = (x[idx * 3 + 2] - lo2) / (hi2 - lo2);

    // resolutions = floor(16 * 1.32^l)
    const float res_tab[N_LEVELS] = {16.f, 21.f, 27.f, 36.f, 48.f, 64.f, 84.f,
                                     111.f, 147.f, 194.f, 256.f, 339.f, 447.f, 590.f};

    const ull* __restrict__ tabs = (const ull*)tables;

    // ======== PHASE 1: encode (2 levels/batch, 16 gathers in flight) ========
    // features go straight to this thread's private smem row -> breaks the
    // register live-range between encode and MLP phases.
    #pragma unroll
    for (int lp = 0; lp < 7; lp++) {
        float wxs[2], wys[2], wzs[2];
        unsigned hidx[16];
        #pragma unroll
        for (int s = 0; s < 2; s++) {
            const int l = lp * 2 + s;
            const float r = res_tab[l];
            float px = xn0 * r, py = xn1 * r, pz = xn2 * r;
            float bx = floorf(px), by = floorf(py), bz = floorf(pz);
            float fx = px - bx, fy = py - by, fz = pz - bz;
            wxs[s] = fx * fx * (3.f - 2.f * fx);
            wys[s] = fy * fy * (3.f - 2.f * fy);
            wzs[s] = fz * fz * (3.f - 2.f * fz);
            unsigned ix = (unsigned)bx, iy = (unsigned)by, iz = (unsigned)bz;
            unsigned hx0 = ix,      hx1 = ix + 1u;
            unsigned hy0 = iy * P1, hy1 = (iy + 1u) * P1;
            unsigned hz0 = iz * P2, hz1 = (iz + 1u) * P2;
            const unsigned base = (unsigned)l << LOG2_T;
            hidx[s * 8 + 0] = base + ((hx0 ^ hy0 ^ hz0) & T_MASK);
            hidx[s * 8 + 1] = base + ((hx0 ^ hy0 ^ hz1) & T_MASK);
            hidx[s * 8 + 2] = base + ((hx0 ^ hy1 ^ hz0) & T_MASK);
            hidx[s * 8 + 3] = base + ((hx0 ^ hy1 ^ hz1) & T_MASK);
            hidx[s * 8 + 4] = base + ((hx1 ^ hy0 ^ hz0) & T_MASK);
            hidx[s * 8 + 5] = base + ((hx1 ^ hy0 ^ hz1) & T_MASK);
            hidx[s * 8 + 6] = base + ((hx1 ^ hy1 ^ hz0) & T_MASK);
            hidx[s * 8 + 7] = base + ((hx1 ^ hy1 ^ hz1) & T_MASK);
        }
        ull cc[16];
        #pragma unroll
        for (int q = 0; q < 16; q++) cc[q] = __ldg(&tabs[hidx[q]]);

        uint32_t v[2];
        #pragma unroll
        for (int s = 0; s < 2; s++) {
            float wx = wxs[s], wy = wys[s], wz = wzs[s];
            float ux = 1.f - wx, uy = 1.f - wy, uz = 1.f - wz;
            float w00 = ux * uy, w01 = ux * wy, w10 = wx * uy, w11 = wx * wy;
            float cw[8] = { w00 * uz, w00 * wz, w01 * uz, w01 * wz,
                            w10 * uz, w10 * wz, w11 * uz, w11 * wz };
            float a0 = 0.f, a1 = 0.f;
            #pragma unroll
            for (int q = 0; q < 8; q++) {
                float2 c = *(float2*)&cc[s * 8 + q];
                a0 = fmaf(cw[q], c.x, a0);
                a1 = fmaf(cw[q], c.y, a1);
            }
            v[s] = bf2u(a0, a1);
        }
        sFeat[tid][lp] = make_uint2(v[0], v[1]);
    }

    // e features -> smem slots 7,8 (cols 28..35)
    {
        const float4* e4 = (const float4*)(e + (size_t)idx * 8);
        float4 ea = __ldg(&e4[0]);
        float4 eb = __ldg(&e4[1]);
        sFeat[tid][7] = make_uint2(bf2u(ea.x, ea.y), bf2u(ea.z, ea.w));
        sFeat[tid][8] = make_uint2(bf2u(eb.x, eb.y), bf2u(eb.z, eb.w));
    }

    // ======== PHASE 2: MLP (reload features, low register pressure) ========
    const __nv_bfloat162 zero2 = __floats2bfloat162_rn(0.f, 0.f);

    __nv_bfloat162 inp2[20];
    #pragma unroll
    for (int q = 0; q < 9; q++) {
        U2B2 u; u.u = sFeat[tid][q];
        inp2[2 * q + 0] = u.b[0];
        inp2[2 * q + 1] = u.b[1];
    }
    inp2[18] = zero2;
    inp2[19] = zero2;

    // ---- layer 1: [36] -> [64], tanh ----
    __nv_bfloat162 h1p[32];
    float h_prev = 0.f;
    #pragma unroll
    for (int j = 0; j < WIDTH; j++) {
        const float4* row = (const float4*)&sW1h[j * W1_STRIDE];
        __nv_bfloat162 acc0 = zero2, acc1 = zero2;
        #pragma unroll
        for (int q = 0; q < 5; q++) {
            F4B2 u; u.f4 = row[q];
            acc0 = __hfma2(inp2[4 * q + 0], u.b2[0], acc0);
            acc1 = __hfma2(inp2[4 * q + 1], u.b2[1], acc1);
            acc0 = __hfma2(inp2[4 * q + 2], u.b2[2], acc0);
            acc1 = __hfma2(inp2[4 * q + 3], u.b2[3], acc1);
        }
        float2 s0 = __bfloat1622float2(acc0);
        float2 s1 = __bfloat1622float2(acc1);
        float h = tanh_fast(s0.x + s0.y + s1.x + s1.y + sB1[j]);
        if (j & 1) h1p[j >> 1] = __floats2bfloat162_rn(h_prev, h); else h_prev = h;
    }

    // ---- layer 2: [64] -> [64], tanh ----
    __nv_bfloat162 h2p[32];
    #pragma unroll
    for (int j = 0; j < WIDTH; j++) {
        const float4* row = (const float4*)&sW2h[j * WIDTH];
        __nv_bfloat162 acc0 = zero2, acc1 = zero2;
        #pragma unroll
        for (int q = 0; q < 8; q++) {
            F4B2 u; u.f4 = row[q];
            acc0 = __hfma2(h1p[4 * q + 0], u.b2[0], acc0);
            acc1 = __hfma2(h1p[4 * q + 1], u.b2[1], acc1);
            acc0 = __hfma2(h1p[4 * q + 2], u.b2[2], acc0);
            acc1 = __hfma2(h1p[4 * q + 3], u.b2[3], acc1);
        }
        float2 s0 = __bfloat1622float2(acc0);
        float2 s1 = __bfloat1622float2(acc1);
        float h = tanh_fast(s0.x + s0.y + s1.x + s1.y + sB2[j]);
        if (j & 1) h2p[j >> 1] = __floats2bfloat162_rn(h_prev, h); else h_prev = h;
    }

    // ---- layer 3: [64] -> [3] (fp32 weights, broadcast LDS) ----
    float o0 = sB3[0], o1 = sB3[1], o2 = sB3[2];
    #pragma unroll
    for (int i = 0; i < 32; i++) {
        float2 hv = __bfloat1622float2(h2p[i]);
        o0 = fmaf(hv.x, sW3[0 * WIDTH + 2 * i],     o0);
        o0 = fmaf(hv.y, sW3[0 * WIDTH + 2 * i + 1], o0);
        o1 = fmaf(hv.x, sW3[1 * WIDTH + 2 * i],     o1);
        o1 = fmaf(hv.y, sW3[1 * WIDTH + 2 * i + 1], o1);
        o2 = fmaf(hv.x, sW3[2 * WIDTH + 2 * i],     o2);
        o2 = fmaf(hv.y, sW3[2 * WIDTH + 2 * i + 1], o2);
    }

    out[idx * 3 + 0] = (o0 + xn0) * (hi0 - lo0) + lo0;
    out[idx * 3 + 1] = (o1 + xn1) * (hi1 - lo1) + lo1;
    out[idx * 3 + 2] = (o2 + xn2) * (hi2 - lo2) + lo2;
}

extern "C" void kernel_launch(void* const* d_in, const int* in_sizes, int n_in,
                              void* d_out, int out_size)
{
    const float* x      = (const float*)d_in[0];
    const float* e      = (const float*)d_in[1];
    const float* tables = (const float*)d_in[2];
    const float* W1     = (const float*)d_in[3];
    const float* b1     = (const float*)d_in[4];
    const float* W2     = (const float*)d_in[5];
    const float* b2     = (const float*)d_in[6];
    const float* W3     = (const float*)d_in[7];
    const float* b3     = (const float*)d_in[8];
    const float* bbox   = (const float*)d_in[9];
    float* out = (float*)d_out;

    int n = in_sizes[0] / 3;
    int grid = (n + NTHREADS - 1) / NTHREADS;
    deformnet_kernel<<<grid, NTHREADS>>>(x, e, tables, W1, b1, W2, b2, W3, b3, bbox, out, n);
}